// round 1
// baseline (speedup 1.0000x reference)
#include <cuda_runtime.h>

#define NB 4
#define NS 2048
#define NE 1024
#define NH 16
#define ND 64
#define AST 65   // smem row stride for attention tiles (64 + 1, kills column conflicts)

// -------- scratch (allocation-free: static device globals) --------
__device__ float g_q[(size_t)NB * NH * NS * ND];
__device__ float g_k[(size_t)NB * NH * NS * ND];
__device__ float g_v[(size_t)NB * NH * NS * ND];
__device__ float g_attn[(size_t)NB * NS * NE];

// ============================================================================
// SGEMM:  C = A @ W^T   (A [M,1024] row-major, W [1024,1024] row-major)
// Tile 128x64x16, 256 threads, 8x4 per-thread micro-tile.
// SCATTER=0: row-major C [M,1024].  SCATTER=1: write [B,H,S,D] (n0 selects head).
// ============================================================================
template <int SCATTER>
__global__ void __launch_bounds__(256)
gemm_nt(const float* __restrict__ A, const float* __restrict__ W,
        float* __restrict__ C) {
    __shared__ float As[16][132];  // [k][m], padded
    __shared__ float Ws[16][68];   // [k][n], padded

    const int tid = threadIdx.x;
    const int tx = tid & 15;        // 0..15 -> 4 n-cols
    const int ty = tid >> 4;        // 0..15 -> 8 m-rows
    const int m0 = blockIdx.y * 128;
    const int n0 = blockIdx.x * 64;
    const int lr = tid >> 2;        // 0..63 load row
    const int lc = (tid & 3) << 2;  // 0,4,8,12 load k-offset

    float acc[8][4];
#pragma unroll
    for (int i = 0; i < 8; i++)
#pragma unroll
        for (int j = 0; j < 4; j++) acc[i][j] = 0.f;

    for (int k0 = 0; k0 < NE; k0 += 16) {
        float4 a0 = *(const float4*)(A + (size_t)(m0 + lr) * NE + k0 + lc);
        float4 a1 = *(const float4*)(A + (size_t)(m0 + lr + 64) * NE + k0 + lc);
        float4 w0 = *(const float4*)(W + (size_t)(n0 + lr) * NE + k0 + lc);
        As[lc + 0][lr] = a0.x; As[lc + 1][lr] = a0.y;
        As[lc + 2][lr] = a0.z; As[lc + 3][lr] = a0.w;
        As[lc + 0][lr + 64] = a1.x; As[lc + 1][lr + 64] = a1.y;
        As[lc + 2][lr + 64] = a1.z; As[lc + 3][lr + 64] = a1.w;
        Ws[lc + 0][lr] = w0.x; Ws[lc + 1][lr] = w0.y;
        Ws[lc + 2][lr] = w0.z; Ws[lc + 3][lr] = w0.w;
        __syncthreads();

#pragma unroll
        for (int kk = 0; kk < 16; kk++) {
            float a[8], b[4];
            *(float4*)(a)     = *(const float4*)(&As[kk][8 * ty]);
            *(float4*)(a + 4) = *(const float4*)(&As[kk][8 * ty + 4]);
            *(float4*)(b)     = *(const float4*)(&Ws[kk][4 * tx]);
#pragma unroll
            for (int i = 0; i < 8; i++)
#pragma unroll
                for (int j = 0; j < 4; j++)
                    acc[i][j] = fmaf(a[i], b[j], acc[i][j]);
        }
        __syncthreads();
    }

    if (SCATTER == 0) {
#pragma unroll
        for (int i = 0; i < 8; i++) {
            int m = m0 + 8 * ty + i;
            float4 r = make_float4(acc[i][0], acc[i][1], acc[i][2], acc[i][3]);
            *(float4*)(C + (size_t)m * NE + n0 + 4 * tx) = r;
        }
    } else {
        // BN == ND == 64 -> whole block is one head
        const int hh = n0 / ND;
#pragma unroll
        for (int i = 0; i < 8; i++) {
            int m = m0 + 8 * ty + i;
            int bb = m / NS, ss = m % NS;
            size_t base = (((size_t)bb * NH + hh) * NS + ss) * ND + 4 * tx;
            float4 r = make_float4(acc[i][0], acc[i][1], acc[i][2], acc[i][3]);
            *(float4*)(C + base) = r;
        }
    }
}

// ============================================================================
// Flash attention (fp32, causal + pad mask), one CTA = (b*h, 64-row q tile).
// 256 threads: thread (ty,tx) owns S/P rows 4ty..4ty+3, cols 4tx..4tx+3 and
// O rows 4ty..4ty+3, d-cols 4tx..4tx+3.
// ============================================================================
__global__ void __launch_bounds__(256)
attn_kernel(const float* __restrict__ Q, const float* __restrict__ K,
            const float* __restrict__ V, const int* __restrict__ amask,
            float* __restrict__ O) {
    extern __shared__ float sm[];
    float* Qs = sm;                 // 64 x AST
    float* Ks = sm + 64 * AST;
    float* Vs = sm + 2 * 64 * AST;
    float* Ps = sm + 3 * 64 * AST;

    const int tid = threadIdx.x;
    const int tx = tid & 15;
    const int ty = tid >> 4;
    const int qt = blockIdx.x;
    const int q0 = qt * 64;
    const int bh = blockIdx.y;
    const int b = bh / NH;
    const int h = bh % NH;

    const float* qbase = Q + (size_t)bh * NS * ND;
    const float* kbase = K + (size_t)bh * NS * ND;
    const float* vbase = V + (size_t)bh * NS * ND;

    // load Q tile (once)
    for (int f = tid; f < 64 * 16; f += 256) {
        int r = f >> 4;
        int c = (f & 15) << 2;
        float4 v4 = *(const float4*)(qbase + (size_t)(q0 + r) * ND + c);
        Qs[r * AST + c + 0] = v4.x; Qs[r * AST + c + 1] = v4.y;
        Qs[r * AST + c + 2] = v4.z; Qs[r * AST + c + 3] = v4.w;
    }

    float acco[4][4];
    float rm[4], rl[4];
#pragma unroll
    for (int i = 0; i < 4; i++) {
        rm[i] = -1e30f; rl[i] = 0.f;
#pragma unroll
        for (int j = 0; j < 4; j++) acco[i][j] = 0.f;
    }

    const float scale = 0.125f;  // 1/sqrt(64)

    for (int kt = 0; kt <= qt; kt++) {
        const int k0 = kt * 64;
        __syncthreads();  // prev PV readers done (and Q tile visible on iter 0)

        for (int f = tid; f < 64 * 16; f += 256) {
            int r = f >> 4;
            int c = (f & 15) << 2;
            float4 kv = *(const float4*)(kbase + (size_t)(k0 + r) * ND + c);
            Ks[r * AST + c + 0] = kv.x; Ks[r * AST + c + 1] = kv.y;
            Ks[r * AST + c + 2] = kv.z; Ks[r * AST + c + 3] = kv.w;
            float4 vv = *(const float4*)(vbase + (size_t)(k0 + r) * ND + c);
            Vs[r * AST + c + 0] = vv.x; Vs[r * AST + c + 1] = vv.y;
            Vs[r * AST + c + 2] = vv.z; Vs[r * AST + c + 3] = vv.w;
        }
        __syncthreads();

        // ---- S = scale * Q K^T ----
        float sacc[4][4];
#pragma unroll
        for (int i = 0; i < 4; i++)
#pragma unroll
            for (int j = 0; j < 4; j++) sacc[i][j] = 0.f;

#pragma unroll 16
        for (int d = 0; d < 64; d++) {
            float a[4], bq[4];
#pragma unroll
            for (int i = 0; i < 4; i++) a[i] = Qs[(4 * ty + i) * AST + d];
#pragma unroll
            for (int j = 0; j < 4; j++) bq[j] = Ks[(4 * tx + j) * AST + d];
#pragma unroll
            for (int i = 0; i < 4; i++)
#pragma unroll
                for (int j = 0; j < 4; j++)
                    sacc[i][j] = fmaf(a[i], bq[j], sacc[i][j]);
        }

        // ---- mask + scale ----
        int pmv[4];
#pragma unroll
        for (int j = 0; j < 4; j++) pmv[j] = amask[b * NS + k0 + 4 * tx + j];
        const bool diag = (kt == qt);
#pragma unroll
        for (int i = 0; i < 4; i++) {
            int qi = q0 + 4 * ty + i;
#pragma unroll
            for (int j = 0; j < 4; j++) {
                int kj = k0 + 4 * tx + j;
                float s = sacc[i][j] * scale;
                if ((diag && kj > qi) || pmv[j] == 0) s = -1e30f;
                sacc[i][j] = s;
            }
        }

        // ---- online softmax (row reductions across the 16 tx lanes) ----
#pragma unroll
        for (int i = 0; i < 4; i++) {
            float mt = fmaxf(fmaxf(sacc[i][0], sacc[i][1]),
                             fmaxf(sacc[i][2], sacc[i][3]));
            mt = fmaxf(mt, __shfl_xor_sync(0xffffffffu, mt, 8));
            mt = fmaxf(mt, __shfl_xor_sync(0xffffffffu, mt, 4));
            mt = fmaxf(mt, __shfl_xor_sync(0xffffffffu, mt, 2));
            mt = fmaxf(mt, __shfl_xor_sync(0xffffffffu, mt, 1));
            float mnew = fmaxf(rm[i], mt);
            float fac = __expf(rm[i] - mnew);
            rm[i] = mnew;

            float psum = 0.f;
#pragma unroll
            for (int j = 0; j < 4; j++) {
                float p = __expf(sacc[i][j] - mnew);
                Ps[(4 * ty + i) * AST + 4 * tx + j] = p;
                psum += p;
            }
            psum += __shfl_xor_sync(0xffffffffu, psum, 8);
            psum += __shfl_xor_sync(0xffffffffu, psum, 4);
            psum += __shfl_xor_sync(0xffffffffu, psum, 2);
            psum += __shfl_xor_sync(0xffffffffu, psum, 1);
            rl[i] = rl[i] * fac + psum;
#pragma unroll
            for (int j = 0; j < 4; j++) acco[i][j] *= fac;
        }
        __syncthreads();

        // ---- O += P V ----
#pragma unroll 16
        for (int j = 0; j < 64; j++) {
            float a[4], vv[4];
#pragma unroll
            for (int i = 0; i < 4; i++) a[i] = Ps[(4 * ty + i) * AST + j];
#pragma unroll
            for (int jj = 0; jj < 4; jj++) vv[jj] = Vs[j * AST + 4 * tx + jj];
#pragma unroll
            for (int i = 0; i < 4; i++)
#pragma unroll
                for (int jj = 0; jj < 4; jj++)
                    acco[i][jj] = fmaf(a[i], vv[jj], acco[i][jj]);
        }
    }

    // ---- epilogue: write merged [B,S,E] ----
#pragma unroll
    for (int i = 0; i < 4; i++) {
        float inv = 1.f / rl[i];
        size_t base = ((size_t)(b * NS + q0 + 4 * ty + i)) * NE + h * ND + 4 * tx;
        float4 r = make_float4(acco[i][0] * inv, acco[i][1] * inv,
                               acco[i][2] * inv, acco[i][3] * inv);
        *(float4*)(O + base) = r;
    }
}

// ============================================================================
// launcher
// ============================================================================
extern "C" void kernel_launch(void* const* d_in, const int* in_sizes, int n_in,
                              void* d_out, int out_size) {
    (void)in_sizes; (void)n_in; (void)out_size;
    const float* x  = (const float*)d_in[0];
    const int*   am = (const int*)d_in[1];
    const float* wq = (const float*)d_in[2];
    const float* wk = (const float*)d_in[3];
    const float* wv = (const float*)d_in[4];
    const float* wo = (const float*)d_in[5];
    float* out = (float*)d_out;

    float *q, *k, *v, *attn;
    cudaGetSymbolAddress((void**)&q, g_q);
    cudaGetSymbolAddress((void**)&k, g_k);
    cudaGetSymbolAddress((void**)&v, g_v);
    cudaGetSymbolAddress((void**)&attn, g_attn);

    const dim3 gg(NE / 64, (NB * NS) / 128);  // (16, 64)

    gemm_nt<1><<<gg, 256>>>(x, wq, q);
    gemm_nt<1><<<gg, 256>>>(x, wk, k);
    gemm_nt<1><<<gg, 256>>>(x, wv, v);

    const int ATTN_SMEM = 4 * 64 * AST * (int)sizeof(float);  // 66560 B
    cudaFuncSetAttribute(attn_kernel,
                         cudaFuncAttributeMaxDynamicSharedMemorySize, ATTN_SMEM);
    attn_kernel<<<dim3(NS / 64, NB * NH), 256, ATTN_SMEM>>>(q, k, v, am, attn);

    gemm_nt<0><<<gg, 256>>>(attn, wo, out);
}